// round 11
// baseline (speedup 1.0000x reference)
#include <cuda_runtime.h>
#include <math.h>

#define Bn 16
#define Ln 4096
#define Cn 1024
#define Kn 16
#define NSPLIT 32
#define CHUNK 128
#define THREADS 512
#define TC 64
#define NTILE 16
#define QSTRIDE 68
#define NEG_INF (__int_as_float(0xff800000))

typedef unsigned long long ull;

__device__ float g_acc[(size_t)Bn * NSPLIT * Kn * Cn];
__device__ float g_m[Bn * NSPLIT * Kn];
__device__ float g_d[Bn * NSPLIT * Kn];

__device__ __forceinline__ ull fma2(ull a, ull b, ull c) {
    ull d;
    asm("fma.rn.f32x2 %0, %1, %2, %3;" : "=l"(d) : "l"(a), "l"(b), "l"(c));
    return d;
}
__device__ __forceinline__ float2 unpack2(ull v) {
    float2 f;
    f.x = __uint_as_float((unsigned)(v & 0xffffffffULL));
    f.y = __uint_as_float((unsigned)(v >> 32));
    return f;
}
__device__ __forceinline__ ull pack2(float a, float b) {
    ull v;
    asm("mov.b64 %0, {%1, %2};" : "=l"(v) : "f"(a), "f"(b));
    return v;
}
__device__ __forceinline__ void cp_async16(unsigned int smem, const void* g) {
    asm volatile("cp.async.cg.shared.global [%0], [%1], 16;" :: "r"(smem), "l"(g));
}
__device__ __forceinline__ void cp_commit() {
    asm volatile("cp.async.commit_group;");
}
template <int N>
__device__ __forceinline__ void cp_wait() {
    asm volatile("cp.async.wait_group %0;" :: "n"(N) : "memory");
}

// SMEM byte offsets (per-block total ~89KB -> 2 blocks/SM)
#define XS0   0                            // 128 l x 64 c fp32 = 32KB
#define XS1   32768
#define QS0   65536                        // 16 k x 68 floats = 4352B
#define QS1   (65536 + 4352)
#define SSOFF 74240                        // scores [16 k][128 l] = 8KB
#define W2OFF (SSOFF + 8192)               // weights [64 lp][16 k] ull = 8KB
#define MKOFF (W2OFF + 8192)               // mask [128] int
#define SMEM_TOTAL (MKOFF + 512)           // 91136

extern "C" __global__ void __launch_bounds__(THREADS, 2)
pool_partial_kernel(const float* __restrict__ x,
                    const int* __restrict__ mask,
                    const float* __restrict__ q) {
    extern __shared__ char smem[];
    unsigned int smem_u32 = (unsigned int)__cvta_generic_to_shared(smem);
    float* s_s = (float*)(smem + SSOFF);
    int* mask_s = (int*)(smem + MKOFF);

    const int tid = threadIdx.x;
    const int w = tid >> 5;
    const int lane = tid & 31;
    const int cg = lane & 7;
    const int kg = lane >> 3;
    const int b = blockIdx.x / NSPLIT;
    const int split = blockIdx.x % NSPLIT;
    const int l0 = split * CHUNK;
    const float* xbase = x + ((size_t)b * Ln + l0) * Cn;

    // ---- prefetch tile 0 (x + q) ----
    {
        unsigned int xd = smem_u32 + XS0;
#pragma unroll
        for (int r = 0; r < 4; ++r) {
            int id = tid + THREADS * r;          // 2048 float4
            int row = id >> 4, c4 = id & 15;
            cp_async16(xd + row * 256 + c4 * 16,
                       xbase + (size_t)row * Cn + c4 * 4);
        }
        if (tid < 256) {
            int qrow = tid >> 4, qc4 = tid & 15;
            cp_async16(smem_u32 + QS0 + qrow * (QSTRIDE * 4) + qc4 * 16,
                       q + qrow * Cn + qc4 * 4);
        }
        cp_commit();
    }
    if (tid < CHUNK) mask_s[tid] = mask[b * Ln + l0 + tid];

    ull acc[8][4];
#pragma unroll
    for (int a = 0; a < 8; ++a)
#pragma unroll
        for (int i = 0; i < 4; ++i) acc[a][i] = 0ULL;

    // ---------------- Phase A: 16 c-tiles of 64 ----------------
    for (int t = 0; t < NTILE; ++t) {
        if (t < NTILE - 1) {
            const int tn = t + 1;
            unsigned int xd = smem_u32 + ((tn & 1) ? XS1 : XS0);
#pragma unroll
            for (int r = 0; r < 4; ++r) {
                int id = tid + THREADS * r;
                int row = id >> 4, c4 = id & 15;
                cp_async16(xd + row * 256 + c4 * 16,
                           xbase + (size_t)row * Cn + tn * TC + c4 * 4);
            }
            if (tid < 256) {
                int qrow = tid >> 4, qc4 = tid & 15;
                cp_async16(smem_u32 + ((tn & 1) ? QS1 : QS0) + qrow * (QSTRIDE * 4) + qc4 * 16,
                           q + qrow * Cn + tn * TC + qc4 * 4);
            }
            cp_commit();
            cp_wait<1>();
        } else {
            cp_wait<0>();
        }
        __syncthreads();

        const float* xs = (const float*)(smem + ((t & 1) ? XS1 : XS0));
        const float* qs = (const float*)(smem + ((t & 1) ? QS1 : QS0));

#pragma unroll
        for (int quad = 0; quad < 2; ++quad) {
            const int cof = cg * 4 + quad * 32;
            ulonglong2 qv[4];
#pragma unroll
            for (int i = 0; i < 4; ++i)
                qv[i] = *(const ulonglong2*)(qs + (kg * 4 + i) * QSTRIDE + cof);
#pragma unroll
            for (int j = 0; j < 8; ++j) {
                ulonglong2 xv = *(const ulonglong2*)(xs + (w * 8 + j) * TC + cof);
#pragma unroll
                for (int i = 0; i < 4; ++i) {
                    acc[j][i] = fma2(xv.x, qv[i].x, acc[j][i]);
                    acc[j][i] = fma2(xv.y, qv[i].y, acc[j][i]);
                }
            }
        }
        __syncthreads();
    }

    // ---- fold + 3-shfl cg reduction + masked write ----
    {
        const float scale = 0.03125f;
#pragma unroll
        for (int j = 0; j < 8; ++j)
#pragma unroll
            for (int i = 0; i < 4; ++i) {
                float2 f = unpack2(acc[j][i]);
                float s = f.x + f.y;
                s += __shfl_xor_sync(0xffffffffu, s, 1);
                s += __shfl_xor_sync(0xffffffffu, s, 2);
                s += __shfl_xor_sync(0xffffffffu, s, 4);
                if (cg == 0) {
                    const int l = w * 8 + j;
                    const int k = kg * 4 + i;
                    s_s[k * CHUNK + l] = mask_s[l] ? (s * scale) : NEG_INF;
                }
            }
    }
    __syncthreads();

    // ---------------- Phase B ----------------
    {
        const int k = w;
        float v0 = s_s[k * CHUNK + lane];
        float v1 = s_s[k * CHUNK + lane + 32];
        float v2 = s_s[k * CHUNK + lane + 64];
        float v3 = s_s[k * CHUNK + lane + 96];
        float m = fmaxf(fmaxf(v0, v1), fmaxf(v2, v3));
#pragma unroll
        for (int off = 16; off; off >>= 1)
            m = fmaxf(m, __shfl_xor_sync(0xffffffffu, m, off));
        float e0, e1, e2, e3;
        if (m == NEG_INF) {
            e0 = e1 = e2 = e3 = 0.f;
        } else {
            e0 = __expf(v0 - m); e1 = __expf(v1 - m);
            e2 = __expf(v2 - m); e3 = __expf(v3 - m);
        }
        float d = e0 + e1 + e2 + e3;
#pragma unroll
        for (int off = 16; off; off >>= 1)
            d += __shfl_xor_sync(0xffffffffu, d, off);
        float* w2f = (float*)(smem + W2OFF);
        {
            int l = lane;
            w2f[(l >> 1) * 32 + k * 2 + (l & 1)] = e0;
            l = lane + 32;
            w2f[(l >> 1) * 32 + k * 2 + (l & 1)] = e1;
            l = lane + 64;
            w2f[(l >> 1) * 32 + k * 2 + (l & 1)] = e2;
            l = lane + 96;
            w2f[(l >> 1) * 32 + k * 2 + (l & 1)] = e3;
        }
        if (lane == 0) {
            g_m[(b * NSPLIT + split) * Kn + k] = m;
            g_d[(b * NSPLIT + split) * Kn + k] = d;
        }
    }
    __syncthreads();

    // -------- Phase C: depth-4 LDG prefetch --------
    {
        const int c0 = tid * 2;
        const ulonglong2* w2v = (const ulonglong2*)(smem + W2OFF);
        ull a2[Kn][2];
#pragma unroll
        for (int k = 0; k < Kn; ++k) { a2[k][0] = 0ULL; a2[k][1] = 0ULL; }

        ull xb0[4], xb1[4];
#pragma unroll
        for (int i = 0; i < 4; ++i) {
            xb0[i] = *(const ull*)(xbase + (size_t)(2 * i) * Cn + c0);
            xb1[i] = *(const ull*)(xbase + (size_t)(2 * i + 1) * Cn + c0);
        }

#pragma unroll 4
        for (int lp = 0; lp < 64; ++lp) {
            const int sl = lp & 3;
            float2 fa = unpack2(xb0[sl]);
            float2 fb = unpack2(xb1[sl]);
            ull v0 = pack2(fa.x, fb.x);
            ull v1 = pack2(fa.y, fb.y);
            if (lp < 60) {
                xb0[sl] = *(const ull*)(xbase + (size_t)(2 * (lp + 4)) * Cn + c0);
                xb1[sl] = *(const ull*)(xbase + (size_t)(2 * (lp + 4) + 1) * Cn + c0);
            }
#pragma unroll
            for (int kp = 0; kp < 8; ++kp) {
                ulonglong2 wp = w2v[lp * 8 + kp];
                a2[2 * kp][0]     = fma2(wp.x, v0, a2[2 * kp][0]);
                a2[2 * kp][1]     = fma2(wp.x, v1, a2[2 * kp][1]);
                a2[2 * kp + 1][0] = fma2(wp.y, v0, a2[2 * kp + 1][0]);
                a2[2 * kp + 1][1] = fma2(wp.y, v1, a2[2 * kp + 1][1]);
            }
        }
        float* ab = g_acc + ((size_t)(b * NSPLIT + split) * Kn) * Cn;
#pragma unroll
        for (int k = 0; k < Kn; ++k) {
            float2 r0 = unpack2(a2[k][0]);
            float2 r1 = unpack2(a2[k][1]);
            float2 o;
            o.x = r0.x + r0.y;
            o.y = r1.x + r1.y;
            *(float2*)(ab + (size_t)k * Cn + c0) = o;
        }
    }
}

// ---------------- Kernel 2: LSE merge (float4, 512 blocks) ----------------
extern "C" __global__ void __launch_bounds__(128)
pool_reduce_kernel(float* __restrict__ out) {
    const int bk = blockIdx.x >> 1;
    const int b = bk >> 4;
    const int k = bk & 15;
    const int ch = blockIdx.x & 1;
    const int tid = threadIdx.x;

    __shared__ float coef[NSPLIT];
    if (tid < NSPLIT) {
        float m = g_m[(b * NSPLIT + tid) * Kn + k];
        float d = g_d[(b * NSPLIT + tid) * Kn + k];
        float M = m;
#pragma unroll
        for (int off = 16; off; off >>= 1)
            M = fmaxf(M, __shfl_xor_sync(0xffffffffu, M, off));
        float t = (m == NEG_INF) ? 0.f : d * __expf(m - M);
        float D = t;
#pragma unroll
        for (int off = 16; off; off >>= 1)
            D += __shfl_xor_sync(0xffffffffu, D, off);
        float c = 0.f;
        if (M != NEG_INF && D > 0.f)
            c = __expf(m - M) / D;
        coef[tid] = c;
    }
    __syncthreads();

    const int c0 = ch * 512 + tid * 4;
    ull o0 = 0ULL, o1 = 0ULL;
    const float* accb = g_acc + ((size_t)b * NSPLIT * Kn + k) * Cn;
#pragma unroll
    for (int s = 0; s < NSPLIT; ++s) {
        ull cs = pack2(coef[s], coef[s]);
        ulonglong2 a = *(const ulonglong2*)(accb + (size_t)s * Kn * Cn + c0);
        o0 = fma2(cs, a.x, o0);
        o1 = fma2(cs, a.y, o1);
    }
    ulonglong2 ov; ov.x = o0; ov.y = o1;
    *(ulonglong2*)(out + ((size_t)(b * Kn + k)) * Cn + c0) = ov;
}

// ---------------- instrumentation dummies (2: lands -s 5 on partial) ----------------
extern "C" __global__ void dummy_pad_kernel() {}

extern "C" void kernel_launch(void* const* d_in, const int* in_sizes, int n_in,
                              void* d_out, int out_size) {
    const float* x  = (const float*)d_in[0];
    const int* mask = (const int*)d_in[1];
    const float* q  = (const float*)d_in[2];
    float* out      = (float*)d_out;

    cudaFuncSetAttribute(pool_partial_kernel,
                         cudaFuncAttributeMaxDynamicSharedMemorySize, SMEM_TOTAL);
    pool_partial_kernel<<<Bn * NSPLIT, THREADS, SMEM_TOTAL>>>(x, mask, q);
    pool_reduce_kernel<<<Bn * Kn * 2, 128>>>(out);
    dummy_pad_kernel<<<1, 32>>>();
    dummy_pad_kernel<<<1, 32>>>();
}

// round 12
// speedup vs baseline: 5.1278x; 5.1278x over previous
#include <cuda_runtime.h>
#include <math.h>

#define Bn 16
#define Ln 4096
#define Cn 1024
#define Kn 16
#define NSPLIT 32
#define CHUNK 128
#define THREADS 512
#define TC 128
#define NTILE 8
#define QSTRIDE 132
#define NEG_INF (__int_as_float(0xff800000))

typedef unsigned long long ull;

__device__ float g_acc[(size_t)Bn * NSPLIT * Kn * Cn];
__device__ float g_m[Bn * NSPLIT * Kn];
__device__ float g_d[Bn * NSPLIT * Kn];

__device__ __forceinline__ ull fma2(ull a, ull b, ull c) {
    ull d;
    asm("fma.rn.f32x2 %0, %1, %2, %3;" : "=l"(d) : "l"(a), "l"(b), "l"(c));
    return d;
}
__device__ __forceinline__ float2 unpack2(ull v) {
    float2 f;
    f.x = __uint_as_float((unsigned)(v & 0xffffffffULL));
    f.y = __uint_as_float((unsigned)(v >> 32));
    return f;
}
__device__ __forceinline__ ull pack2(float a, float b) {
    ull v;
    asm("mov.b64 %0, {%1, %2};" : "=l"(v) : "f"(a), "f"(b));
    return v;
}
__device__ __forceinline__ void cp_async16(unsigned int smem, const void* g) {
    asm volatile("cp.async.cg.shared.global [%0], [%1], 16;" :: "r"(smem), "l"(g));
}
__device__ __forceinline__ void cp_commit() {
    asm volatile("cp.async.commit_group;");
}
template <int N>
__device__ __forceinline__ void cp_wait() {
    asm volatile("cp.async.wait_group %0;" :: "n"(N) : "memory");
}

// SMEM byte offsets
#define XS0   0
#define XS1   65536
#define QS0   131072
#define QS1   (131072 + 8448)
#define SSOFF (131072 + 16896)
#define W2OFF (SSOFF + Kn * CHUNK * 4)
#define MKOFF (W2OFF + 64 * Kn * 8)
#define SMEM_TOTAL (MKOFF + CHUNK * 4)

extern "C" __global__ void __launch_bounds__(THREADS, 1)
pool_partial_kernel(const float* __restrict__ x,
                    const int* __restrict__ mask,
                    const float* __restrict__ q) {
    extern __shared__ char smem[];
    unsigned int smem_u32 = (unsigned int)__cvta_generic_to_shared(smem);
    float* s_s = (float*)(smem + SSOFF);
    int* mask_s = (int*)(smem + MKOFF);

    const int tid = threadIdx.x;
    const int w = tid >> 5;
    const int lane = tid & 31;
    const int cg = lane & 7;
    const int kg = lane >> 3;
    const int b = blockIdx.x / NSPLIT;
    const int split = blockIdx.x % NSPLIT;
    const int l0 = split * CHUNK;
    const float* xbase = x + ((size_t)b * Ln + l0) * Cn;

    // ---- prefetch tile 0 (x + q) ----
    {
        unsigned int xd = smem_u32 + XS0;
#pragma unroll
        for (int r = 0; r < 8; ++r) {
            int id = tid + THREADS * r;
            int row = id >> 5, c4 = id & 31;
            cp_async16(xd + row * 512 + c4 * 16,
                       xbase + (size_t)row * Cn + c4 * 4);
        }
        int qrow = tid >> 5, qc4 = tid & 31;
        cp_async16(smem_u32 + QS0 + qrow * (QSTRIDE * 4) + qc4 * 16,
                   q + qrow * Cn + qc4 * 4);
        cp_commit();
    }
    if (tid < CHUNK) mask_s[tid] = mask[b * Ln + l0 + tid];

    ull acc[8][4];
#pragma unroll
    for (int a = 0; a < 8; ++a)
#pragma unroll
        for (int i = 0; i < 4; ++i) acc[a][i] = 0ULL;

    // ---------------- Phase A ----------------
    for (int t = 0; t < NTILE; ++t) {
        if (t < NTILE - 1) {
            const int tn = t + 1;
            unsigned int xd = smem_u32 + ((tn & 1) ? XS1 : XS0);
#pragma unroll
            for (int r = 0; r < 8; ++r) {
                int id = tid + THREADS * r;
                int row = id >> 5, c4 = id & 31;
                cp_async16(xd + row * 512 + c4 * 16,
                           xbase + (size_t)row * Cn + tn * TC + c4 * 4);
            }
            int qrow = tid >> 5, qc4 = tid & 31;
            cp_async16(smem_u32 + ((tn & 1) ? QS1 : QS0) + qrow * (QSTRIDE * 4) + qc4 * 16,
                       q + qrow * Cn + tn * TC + qc4 * 4);
            cp_commit();
            cp_wait<1>();
        } else {
            cp_wait<0>();
        }
        __syncthreads();

        const float* xs = (const float*)(smem + ((t & 1) ? XS1 : XS0));
        const float* qs = (const float*)(smem + ((t & 1) ? QS1 : QS0));

#pragma unroll
        for (int quad = 0; quad < 4; ++quad) {
            const int cof = cg * 4 + quad * 32;
            ulonglong2 qv[4];
#pragma unroll
            for (int i = 0; i < 4; ++i)
                qv[i] = *(const ulonglong2*)(qs + (kg * 4 + i) * QSTRIDE + cof);
#pragma unroll
            for (int j = 0; j < 8; ++j) {
                ulonglong2 xv = *(const ulonglong2*)(xs + (w * 8 + j) * TC + cof);
#pragma unroll
                for (int i = 0; i < 4; ++i) {
                    acc[j][i] = fma2(xv.x, qv[i].x, acc[j][i]);
                    acc[j][i] = fma2(xv.y, qv[i].y, acc[j][i]);
                }
            }
        }
        __syncthreads();
    }

    // ---- fold + 3-shfl cg reduction + masked write ----
    {
        const float scale = 0.03125f;
#pragma unroll
        for (int j = 0; j < 8; ++j)
#pragma unroll
            for (int i = 0; i < 4; ++i) {
                float2 f = unpack2(acc[j][i]);
                float s = f.x + f.y;
                s += __shfl_xor_sync(0xffffffffu, s, 1);
                s += __shfl_xor_sync(0xffffffffu, s, 2);
                s += __shfl_xor_sync(0xffffffffu, s, 4);
                if (cg == 0) {
                    const int l = w * 8 + j;
                    const int k = kg * 4 + i;
                    s_s[k * CHUNK + l] = mask_s[l] ? (s * scale) : NEG_INF;
                }
            }
    }
    __syncthreads();

    // ---------------- Phase B ----------------
    {
        const int k = w;
        float v0 = s_s[k * CHUNK + lane];
        float v1 = s_s[k * CHUNK + lane + 32];
        float v2 = s_s[k * CHUNK + lane + 64];
        float v3 = s_s[k * CHUNK + lane + 96];
        float m = fmaxf(fmaxf(v0, v1), fmaxf(v2, v3));
#pragma unroll
        for (int off = 16; off; off >>= 1)
            m = fmaxf(m, __shfl_xor_sync(0xffffffffu, m, off));
        float e0, e1, e2, e3;
        if (m == NEG_INF) {
            e0 = e1 = e2 = e3 = 0.f;
        } else {
            e0 = __expf(v0 - m); e1 = __expf(v1 - m);
            e2 = __expf(v2 - m); e3 = __expf(v3 - m);
        }
        float d = e0 + e1 + e2 + e3;
#pragma unroll
        for (int off = 16; off; off >>= 1)
            d += __shfl_xor_sync(0xffffffffu, d, off);
        float* w2f = (float*)(smem + W2OFF);
        {
            int l = lane;
            w2f[(l >> 1) * 32 + k * 2 + (l & 1)] = e0;
            l = lane + 32;
            w2f[(l >> 1) * 32 + k * 2 + (l & 1)] = e1;
            l = lane + 64;
            w2f[(l >> 1) * 32 + k * 2 + (l & 1)] = e2;
            l = lane + 96;
            w2f[(l >> 1) * 32 + k * 2 + (l & 1)] = e3;
        }
        if (lane == 0) {
            g_m[(b * NSPLIT + split) * Kn + k] = m;
            g_d[(b * NSPLIT + split) * Kn + k] = d;
        }
    }
    __syncthreads();

    // -------- Phase C: depth-4 LDG prefetch --------
    {
        const int c0 = tid * 2;
        const ulonglong2* w2v = (const ulonglong2*)(smem + W2OFF);
        ull a2[Kn][2];
#pragma unroll
        for (int k = 0; k < Kn; ++k) { a2[k][0] = 0ULL; a2[k][1] = 0ULL; }

        ull xb0[4], xb1[4];
#pragma unroll
        for (int i = 0; i < 4; ++i) {
            xb0[i] = *(const ull*)(xbase + (size_t)(2 * i) * Cn + c0);
            xb1[i] = *(const ull*)(xbase + (size_t)(2 * i + 1) * Cn + c0);
        }

#pragma unroll 4
        for (int lp = 0; lp < 64; ++lp) {
            const int sl = lp & 3;
            float2 fa = unpack2(xb0[sl]);
            float2 fb = unpack2(xb1[sl]);
            ull v0 = pack2(fa.x, fb.x);
            ull v1 = pack2(fa.y, fb.y);
            if (lp < 60) {
                xb0[sl] = *(const ull*)(xbase + (size_t)(2 * (lp + 4)) * Cn + c0);
                xb1[sl] = *(const ull*)(xbase + (size_t)(2 * (lp + 4) + 1) * Cn + c0);
            }
#pragma unroll
            for (int kp = 0; kp < 8; ++kp) {
                ulonglong2 wp = w2v[lp * 8 + kp];
                a2[2 * kp][0]     = fma2(wp.x, v0, a2[2 * kp][0]);
                a2[2 * kp][1]     = fma2(wp.x, v1, a2[2 * kp][1]);
                a2[2 * kp + 1][0] = fma2(wp.y, v0, a2[2 * kp + 1][0]);
                a2[2 * kp + 1][1] = fma2(wp.y, v1, a2[2 * kp + 1][1]);
            }
        }
        float* ab = g_acc + ((size_t)(b * NSPLIT + split) * Kn) * Cn;
#pragma unroll
        for (int k = 0; k < Kn; ++k) {
            float2 r0 = unpack2(a2[k][0]);
            float2 r1 = unpack2(a2[k][1]);
            float2 o;
            o.x = r0.x + r0.y;
            o.y = r1.x + r1.y;
            *(float2*)(ab + (size_t)k * Cn + c0) = o;
        }
    }
}

// ---------------- Kernel 2: LSE merge ----------------
extern "C" __global__ void __launch_bounds__(128)
pool_reduce_kernel(float* __restrict__ out) {
    const int bk = blockIdx.x >> 2;
    const int b = bk >> 4;
    const int k = bk & 15;
    const int cq = blockIdx.x & 3;
    const int tid = threadIdx.x;

    __shared__ float coef[NSPLIT];
    if (tid < NSPLIT) {
        float m = g_m[(b * NSPLIT + tid) * Kn + k];
        float d = g_d[(b * NSPLIT + tid) * Kn + k];
        float M = m;
#pragma unroll
        for (int off = 16; off; off >>= 1)
            M = fmaxf(M, __shfl_xor_sync(0xffffffffu, M, off));
        float t = (m == NEG_INF) ? 0.f : d * __expf(m - M);
        float D = t;
#pragma unroll
        for (int off = 16; off; off >>= 1)
            D += __shfl_xor_sync(0xffffffffu, D, off);
        float c = 0.f;
        if (M != NEG_INF && D > 0.f)
            c = __expf(m - M) / D;
        coef[tid] = c;
    }
    __syncthreads();

    const int c0 = cq * 256 + tid * 2;
    ull o = 0ULL;
    const float* accb = g_acc + ((size_t)b * NSPLIT * Kn + k) * Cn;
#pragma unroll
    for (int s = 0; s < NSPLIT; ++s) {
        ull cs = pack2(coef[s], coef[s]);
        ull a = *(const ull*)(accb + (size_t)s * Kn * Cn + c0);
        o = fma2(cs, a, o);
    }
    *(ull*)(out + ((size_t)(b * Kn + k)) * Cn + c0) = o;
}

// ---------------- instrumentation: ONE dummy BETWEEN P and R ----------------
// Stream has 2 leading launches; sequence (P, D, R) repeated puts capture
// position 6 (= -s 5 -c 1) on pool_partial_kernel: 1X 2X 3P 4D 5R 6P.
extern "C" __global__ void dummy_pad_kernel() {}

extern "C" void kernel_launch(void* const* d_in, const int* in_sizes, int n_in,
                              void* d_out, int out_size) {
    const float* x  = (const float*)d_in[0];
    const int* mask = (const int*)d_in[1];
    const float* q  = (const float*)d_in[2];
    float* out      = (float*)d_out;

    cudaFuncSetAttribute(pool_partial_kernel,
                         cudaFuncAttributeMaxDynamicSharedMemorySize, SMEM_TOTAL);
    pool_partial_kernel<<<Bn * NSPLIT, THREADS, SMEM_TOTAL>>>(x, mask, q);
    dummy_pad_kernel<<<1, 32>>>();
    pool_reduce_kernel<<<Bn * Kn * 4, 128>>>(out);
}